// round 14
// baseline (speedup 1.0000x reference)
#include <cuda_runtime.h>
#include <cstdint>

typedef signed char s8;

#define BB 128
#define CC 64
#define HH_ 56
#define WW_ 56
#define HWP 3136
#define NELEM (BB*CC*HWP)       // 25690112
#define NWORDS (NELEM/4)        // 6422528

// ---------------- persistent device scratch ----------------
__device__ alignas(16) float g_out1[NELEM];     // stage1 output, NHWC fp32
__device__ alignas(16) int   g_xq[NWORDS];      // stage1 act k-plane, NHWC int8 (k in [-7,7])
__device__ alignas(16) int   g_xc[NWORDS];      // stage1 act c-plane (+-1 for |k| in {5,7})
__device__ alignas(16) int   g_x1[NWORDS];      // stage2 act k-plane
__device__ alignas(16) int   g_x1c[NWORDS];     // stage2 act c-plane
__device__ alignas(16) int   g_wgt1[9216];      // signs +-1, [tap][co][ci] bytes
__device__ alignas(16) int   g_wgt2[9216];
__device__ float g_sw1[64], g_sw2[64];
__device__ float g_qw1[64], g_qb1[64], g_qw2[64], g_qb2[64];
__device__ float g_div7[15];                    // fl(k/7), k=-7..7
__device__ unsigned g_T1bits, g_T2bits;

// conv smem: s_k 4224 words (4 rows x 66 px x 16 w), s_c same, s_w 9216 words
#define CONV_SMEM_WORDS (4224 + 4224 + 9216)
#define CONV_SMEM_BYTES (CONV_SMEM_WORDS*4)     // 70656

__global__ void init_kernel() {
  g_T1bits = 0u; g_T2bits = 0u;
  #pragma unroll
  for (int k = -7; k <= 7; k++) g_div7[k+7] = __fdiv_rn((float)k, 7.f);
}

// ---------------- global abs-max over x ----------------
__global__ void absmax_kernel(const float* __restrict__ x) {
  const float4* x4 = (const float4*)x;
  float m = 0.f;
  for (int i = blockIdx.x*blockDim.x + threadIdx.x; i < NWORDS; i += gridDim.x*blockDim.x) {
    float4 v = x4[i];
    m = fmaxf(m, fmaxf(fmaxf(fabsf(v.x), fabsf(v.y)), fmaxf(fabsf(v.z), fabsf(v.w))));
  }
  #pragma unroll
  for (int o = 16; o; o >>= 1) m = fmaxf(m, __shfl_xor_sync(0xFFFFFFFFu, m, o));
  if ((threadIdx.x & 31) == 0) atomicMax(&g_T1bits, __float_as_uint(m));
}

// ---------------- helpers ----------------
__device__ __forceinline__ double warp_sumd(double v) {
  #pragma unroll
  for (int o = 16; o; o >>= 1) v += __shfl_xor_sync(0xFFFFFFFFu, v, o);
  return v;
}
__device__ __forceinline__ float warp_maxf(float v) {
  #pragma unroll
  for (int o = 16; o; o >>= 1) v = fmaxf(v, __shfl_xor_sync(0xFFFFFFFFu, v, o));
  return v;
}
__device__ __forceinline__ float quant_val(float x, float T, float n) {
  float c = fminf(fmaxf(x, -T), T);
  float r = __fdiv_rn(c, T);
  float q = __fdiv_rn(rintf(__fmul_rn(r, n)), n);
  return __fmul_rn(q, T);
}
__device__ __forceinline__ int cplane(int k) {
  int a = k < 0 ? -k : k;
  return (a == 5 || a == 7) ? (k > 0 ? 1 : -1) : 0;
}
__device__ __forceinline__ uint32_t smem_u32(const void* p) {
  return (uint32_t)__cvta_generic_to_shared(p);
}
__device__ __forceinline__ void ldsm4(uint32_t* r, uint32_t a) {
  asm volatile("ldmatrix.sync.aligned.m8n8.x4.shared.b16 {%0,%1,%2,%3}, [%4];"
    : "=r"(r[0]), "=r"(r[1]), "=r"(r[2]), "=r"(r[3]) : "r"(a));
}
__device__ __forceinline__ void ldsm2(uint32_t* r, uint32_t a) {
  asm volatile("ldmatrix.sync.aligned.m8n8.x2.shared.b16 {%0,%1}, [%2];"
    : "=r"(r[0]), "=r"(r[1]) : "r"(a));
}
__device__ __forceinline__ void mma_s8(int* c, const uint32_t* a, const uint32_t* b) {
  asm volatile("mma.sync.aligned.m16n8k32.row.col.s32.s8.s8.s32 "
    "{%0,%1,%2,%3}, {%4,%5,%6,%7}, {%8,%9}, {%0,%1,%2,%3};"
    : "+r"(c[0]), "+r"(c[1]), "+r"(c[2]), "+r"(c[3])
    : "r"(a[0]), "r"(a[1]), "r"(a[2]), "r"(a[3]), "r"(b[0]), "r"(b[1]));
}
// epilogue: y = sw*Su*2^-13 (exact TF32 conv); aq = round(y/576*1023)/1023*576;
//           o = aq*qw + qb + k/7; clip [-1,1]
__device__ __forceinline__ float epi(int Sk, int Sc, float swv, float qwv, float qbv, float kv) {
  int Su = 1170*Sk + 2*Sc;
  float y  = __fmul_rn((float)Su, __fmul_rn(swv, 0x1p-13f));
  float m  = rintf(__fmul_rn(__fdiv_rn(y, 576.f), 1023.f));
  float aq = __fmul_rn(__fdiv_rn(m, 1023.f), 576.f);
  float ov = __fadd_rn(__fadd_rn(__fmul_rn(aq, qwv), qbv), kv);
  return fminf(fmaxf(ov, -1.f), 1.f);
}

// ---------------- weight + BN prep ----------------
__global__ void prep_kernel(const float* __restrict__ w1, const float* __restrict__ w2,
                            const float* __restrict__ g1, const float* __restrict__ b1,
                            const float* __restrict__ m1, const float* __restrict__ v1,
                            const float* __restrict__ g2, const float* __restrict__ b2,
                            const float* __restrict__ m2, const float* __restrict__ v2) {
  int wid = threadIdx.x >> 5, lane = threadIdx.x & 31;
  for (int pass = 0; pass < 2; pass++) {
    const float* wsrc = pass ? w2 : w1;
    int* wdst = pass ? g_wgt2 : g_wgt1;
    float* swdst = pass ? g_sw2 : g_sw1;
    for (int co = wid; co < 64; co += 16) {
      const float* w = wsrc + co*576;
      double s = 0.0;
      for (int i = lane; i < 576; i += 32) s += (double)w[i];
      s = warp_sumd(s);
      double mean = s / 576.0;
      double s2 = 0.0, sa = 0.0;
      for (int i = lane; i < 576; i += 32) {
        double d = (double)w[i] - mean; s2 += d*d; sa += fabs(d);
      }
      s2 = warp_sumd(s2); sa = warp_sumd(sa);
      double stdv = sqrt(s2 / 575.0);
      double mabs = (sa / 576.0) / stdv;
      if (lane == 0) swdst[co] = (float)exp2(rint(log2(mabs)));
      // pack signs: word = [tap][co][wci], bytes = ci = wci*4+b ; tap = kh*3+kw
      for (int widx = lane; widx < 144; widx += 32) {
        int tap = widx >> 4, wci = widx & 15;
        unsigned word = 0;
        #pragma unroll
        for (int b = 0; b < 4; b++) {
          double d = (double)w[(wci*4 + b)*9 + tap] - mean;
          unsigned byte = (d >= 0.0) ? 0x01u : 0xFFu;
          word |= byte << (8*b);
        }
        wdst[(tap*64 + co)*16 + wci] = (int)word;
      }
    }
  }
  __syncthreads();
  if (wid < 2) {
    const float* gg = wid ? g2 : g1;
    const float* bt = wid ? b2 : b1;
    const float* mm = wid ? m2 : m1;
    const float* vv = wid ? v2 : v1;
    float* qwd = wid ? g_qw2 : g_qw1;
    float* qbd = wid ? g_qb2 : g_qb1;
    float wv[2], bv[2];
    float mw = 0.f, mb = 0.f;
    #pragma unroll
    for (int q = 0; q < 2; q++) {
      int c = lane + q*32;
      float stdv = __fsqrt_rn(__fadd_rn(vv[c], 1e-5f));
      float wq = __fdiv_rn(gg[c], stdv);
      float bq = __fsub_rn(bt[c], __fmul_rn(wq, mm[c]));
      wv[q] = wq; bv[q] = bq;
      mw = fmaxf(mw, fabsf(wq)); mb = fmaxf(mb, fabsf(bq));
    }
    mw = warp_maxf(mw); mb = warp_maxf(mb);
    float Tw = fminf(fmaxf(mw, 1e-10f), 255.f);
    float Tb = fminf(fmaxf(mb, 1e-10f), 255.f);
    #pragma unroll
    for (int q = 0; q < 2; q++) {
      int c = lane + q*32;
      qwd[c] = quant_val(wv[q], Tw, 7.f);
      qbd[c] = quant_val(bv[q], Tb, 4095.f);
    }
  }
}

// ---------------- quantize x + NCHW -> NHWC int8 (k-plane + c-plane) ----------------
__global__ void qtrans_kernel(const float* __restrict__ x) {
  __shared__ s8 sm[64][68];
  int n = blockIdx.y;
  int hw0 = blockIdx.x * 64;
  float T = fminf(fmaxf(__uint_as_float(g_T1bits), 1e-10f), 255.f);
  for (int i = threadIdx.x; i < 4096; i += 256) {
    int c = i >> 6, hwl = i & 63;
    float v = x[((size_t)n*CC + c)*HWP + hw0 + hwl];
    float cl = fminf(fmaxf(v, -T), T);
    int k = (int)rintf(__fmul_rn(__fdiv_rn(cl, T), 7.f));
    sm[hwl][c] = (s8)k;
  }
  __syncthreads();
  for (int i = threadIdx.x; i < 1024; i += 256) {
    int hwl = i >> 4, c4 = (i & 15) << 2;
    unsigned kw = 0, cw = 0;
    #pragma unroll
    for (int b = 0; b < 4; b++) {
      int kk = (int)sm[hwl][c4+b];
      kw |= ((unsigned)kk & 255u) << (8*b);
      cw |= ((unsigned)cplane(kk) & 255u) << (8*b);
    }
    int idx = (n*HWP + hw0 + hwl)*16 + (c4 >> 2);
    g_xq[idx] = (int)kw;
    g_xc[idx] = (int)cw;
  }
}

// ---------------- conv: IMMA implicit GEMM, 2 output rows per block ----------------
// block 256 thr = 8 warps; warp w = co-tile (8 co). M = 2 rows x 56 px (pad 64) = 8 m16 tiles.
template<int STAGE>
__global__ void __launch_bounds__(256,2) conv_kernel(float* __restrict__ outp) {
  extern __shared__ int s_dyn[];
  int* s_k = s_dyn;            // [slot 0..3][66 px][16 words]
  int* s_c = s_dyn + 4224;
  int* s_w = s_dyn + 8448;     // [tap][co][16 words]
  int bh = blockIdx.x, n = blockIdx.y;
  int h0 = bh*2;
  int t = threadIdx.x, lane = t & 31, wrp = t >> 5;
  const int*   actk = (STAGE == 1) ? g_xq   : g_x1;
  const int*   actc = (STAGE == 1) ? g_xc   : g_x1c;
  const int*   wgt  = (STAGE == 1) ? g_wgt1 : g_wgt2;
  const float* sw   = (STAGE == 1) ? g_sw1  : g_sw2;
  const float* qw   = (STAGE == 1) ? g_qw1  : g_qw2;
  const float* qb   = (STAGE == 1) ? g_qb1  : g_qb2;

  for (int i = t; i < 2304; i += 256) ((int4*)s_w)[i] = ((const int4*)wgt)[i];
  int4 z4 = make_int4(0,0,0,0);
  for (int i = t; i < 2112; i += 256) ((int4*)s_dyn)[i] = z4;   // zero both act planes
  __syncthreads();
  // fill rows: slot s holds input row h0-1+s at padded px 1..56
  for (int i = t; i < 1792; i += 256) {
    int plane = i / 896, r = i % 896, slot = r / 224, seg = r % 224;
    int hr = h0 - 1 + slot;
    if (hr >= 0 && hr < HH_) {
      const int4* src = (const int4*)(plane ? actc : actk);
      int4* dst = (int4*)(plane ? s_c : s_k);
      dst[slot*264 + 4 + seg] = src[((size_t)n*HWP + hr*WW_)*4 + seg];
    }
  }
  __syncthreads();

  int acck[8][4], accc[8][4];
  #pragma unroll
  for (int mt = 0; mt < 8; mt++)
    #pragma unroll
    for (int e = 0; e < 4; e++) { acck[mt][e] = 0; accc[mt][e] = 0; }

  // per-thread ldmatrix row geometry
  uint32_t px_off = (lane & 7) + ((lane >> 3) & 1)*8;   // row within m16 tile
  uint32_t byoff  = (uint32_t)(lane >> 4)*16;           // k-half select
  uint32_t kbase = smem_u32(s_k), cbase = smem_u32(s_c), wbase = smem_u32(s_w);
  uint32_t bco = (lane & 7), bhalf = (lane >> 3) & 1;   // B frag rows (t<16 used)

  #pragma unroll
  for (int kh = 0; kh < 3; kh++) {
    #pragma unroll
    for (int kw = 0; kw < 3; kw++) {
      int tap = kh*3 + kw;
      #pragma unroll
      for (int ch = 0; ch < 2; ch++) {
        uint32_t breg[2];
        uint32_t ba = wbase + ((tap*64 + wrp*8 + bco)*64) + (uint32_t)ch*32 + bhalf*16;
        ldsm2(breg, ba);
        #pragma unroll
        for (int mt = 0; mt < 8; mt++) {
          int rb = mt >> 2, pxb = (mt & 3)*16;
          uint32_t off = (((uint32_t)(kh + rb)*66 + pxb + px_off + kw)*64)
                       + (uint32_t)ch*32 + byoff;
          uint32_t a[4];
          ldsm4(a, kbase + off);
          mma_s8(acck[mt], a, breg);
          ldsm4(a, cbase + off);
          mma_s8(accc[mt], a, breg);
        }
      }
    }
  }

  // ---------------- epilogue ----------------
  const s8* sk8 = (const s8*)s_k;
  int co0 = wrp*8 + (lane & 3)*2;
  float sw0 = sw[co0], sw1 = sw[co0+1];
  float qw0 = qw[co0], qw1 = qw[co0+1];
  float qb0 = qb[co0], qb1 = qb[co0+1];
  float lmax = 0.f;

  #pragma unroll
  for (int mt = 0; mt < 8; mt++) {
    int hh = mt >> 2;
    int p0 = (mt & 3)*16 + (lane >> 2);
    int p1 = p0 + 8;
    bool v1ok = ((mt & 3) < 3);                 // p1 < 56 iff m-subtile < 3
    int sbase = ((1 + hh)*66 + 1)*64;           // center-tap row, padded +1
    int k00 = sk8[sbase + p0*64 + co0];
    int k01 = sk8[sbase + p0*64 + co0 + 1];
    float o00 = epi(acck[mt][0], accc[mt][0], sw0, qw0, qb0, g_div7[k00+7]);
    float o01 = epi(acck[mt][1], accc[mt][1], sw1, qw1, qb1, g_div7[k01+7]);
    float o10 = 0.f, o11 = 0.f;
    if (v1ok) {
      int k10 = sk8[sbase + p1*64 + co0];
      int k11 = sk8[sbase + p1*64 + co0 + 1];
      o10 = epi(acck[mt][2], accc[mt][2], sw0, qw0, qb0, g_div7[k10+7]);
      o11 = epi(acck[mt][3], accc[mt][3], sw1, qw1, qb1, g_div7[k11+7]);
    }
    if (STAGE == 1) {
      float2* d0 = (float2*)&g_out1[((size_t)n*HWP + (h0 + hh)*WW_ + p0)*64 + co0];
      *d0 = make_float2(o00, o01);
      if (v1ok) {
        float2* d1 = (float2*)&g_out1[((size_t)n*HWP + (h0 + hh)*WW_ + p1)*64 + co0];
        *d1 = make_float2(o10, o11);
      }
      lmax = fmaxf(lmax, fmaxf(fmaxf(fabsf(o00), fabsf(o01)),
                               fmaxf(fabsf(o10), fabsf(o11))));
    } else {
      acck[mt][0] = __float_as_int(o00);
      acck[mt][1] = __float_as_int(o01);
      acck[mt][2] = __float_as_int(o10);
      acck[mt][3] = __float_as_int(o11);
    }
  }

  if (STAGE == 1) {
    float lm = warp_maxf(lmax);
    if (lane == 0) atomicMax(&g_T2bits, __float_as_uint(lm));
  } else {
    __syncthreads();                           // all shortcut reads done
    float* s_out = (float*)s_dyn;              // 64 co x 113 stride, px_lin = hh*56+p
    #pragma unroll
    for (int mt = 0; mt < 8; mt++) {
      int hh = mt >> 2;
      int p0 = (mt & 3)*16 + (lane >> 2);
      s_out[co0*113 + hh*56 + p0]       = __int_as_float(acck[mt][0]);
      s_out[(co0+1)*113 + hh*56 + p0]   = __int_as_float(acck[mt][1]);
      if ((mt & 3) < 3) {
        s_out[co0*113 + hh*56 + p0+8]     = __int_as_float(acck[mt][2]);
        s_out[(co0+1)*113 + hh*56 + p0+8] = __int_as_float(acck[mt][3]);
      }
    }
    __syncthreads();
    for (int i = t; i < 7168; i += 256) {
      int co = i / 112, pl = i % 112, hh = pl / 56, p = pl % 56;
      outp[((size_t)(n*CC + co)*HH_ + h0 + hh)*WW_ + p] = s_out[co*113 + pl];
    }
  }
}

// ---------------- quantize stage1 output -> int8 NHWC (both planes) ----------------
__global__ void quant2_kernel() {
  float T = fminf(fmaxf(__uint_as_float(g_T2bits), 1e-10f), 255.f);
  const float4* src = (const float4*)g_out1;
  for (int i = blockIdx.x*blockDim.x + threadIdx.x; i < NWORDS; i += gridDim.x*blockDim.x) {
    float4 v = src[i];
    int k0 = (int)rintf(__fmul_rn(__fdiv_rn(fminf(fmaxf(v.x, -T), T), T), 7.f));
    int k1 = (int)rintf(__fmul_rn(__fdiv_rn(fminf(fmaxf(v.y, -T), T), T), 7.f));
    int k2 = (int)rintf(__fmul_rn(__fdiv_rn(fminf(fmaxf(v.z, -T), T), T), 7.f));
    int k3 = (int)rintf(__fmul_rn(__fdiv_rn(fminf(fmaxf(v.w, -T), T), T), 7.f));
    g_x1[i]  = (k0 & 255) | ((k1 & 255) << 8) | ((k2 & 255) << 16) | ((k3 & 255) << 24);
    g_x1c[i] = (cplane(k0) & 255) | ((cplane(k1) & 255) << 8)
             | ((cplane(k2) & 255) << 16) | ((cplane(k3) & 255) << 24);
  }
}

// ---------------- launcher ----------------
extern "C" void kernel_launch(void* const* d_in, const int* in_sizes, int n_in,
                              void* d_out, int out_size) {
  const float* x  = (const float*)d_in[0];
  const float* w1 = (const float*)d_in[1];
  const float* w2 = (const float*)d_in[2];
  const float* g1 = (const float*)d_in[3];
  const float* b1 = (const float*)d_in[4];
  const float* m1 = (const float*)d_in[5];
  const float* v1 = (const float*)d_in[6];
  const float* g2 = (const float*)d_in[7];
  const float* b2 = (const float*)d_in[8];
  const float* m2 = (const float*)d_in[9];
  const float* v2 = (const float*)d_in[10];
  float* out = (float*)d_out;

  cudaFuncSetAttribute(conv_kernel<1>, cudaFuncAttributeMaxDynamicSharedMemorySize, CONV_SMEM_BYTES);
  cudaFuncSetAttribute(conv_kernel<2>, cudaFuncAttributeMaxDynamicSharedMemorySize, CONV_SMEM_BYTES);

  init_kernel<<<1, 1>>>();
  absmax_kernel<<<1024, 256>>>(x);
  prep_kernel<<<1, 512>>>(w1, w2, g1, b1, m1, v1, g2, b2, m2, v2);
  qtrans_kernel<<<dim3(49, BB), 256>>>(x);
  conv_kernel<1><<<dim3(28, BB), 256, CONV_SMEM_BYTES>>>(out);
  quant2_kernel<<<4096, 256>>>();
  conv_kernel<2><<<dim3(28, BB), 256, CONV_SMEM_BYTES>>>(out);
}